// round 1
// baseline (speedup 1.0000x reference)
#include <cuda_runtime.h>
#include <cuda_bf16.h>

#define NSITES 500000
#define C1 128
#define CH 64
#define C2 128
#define EPS 1e-5f

// h = silu(bn1(features @ W1)), [N, 64]
__device__ float g_h[NSITES * CH];

// ---------- packed f32x2 helpers ----------
__device__ __forceinline__ void fma2(unsigned long long& d, unsigned long long a, unsigned long long b) {
    asm("fma.rn.f32x2 %0, %1, %2, %0;" : "+l"(d) : "l"(a), "l"(b));
}
__device__ __forceinline__ unsigned long long pk2(float x) {
    unsigned long long r;
    asm("mov.b64 %0, {%1, %1};" : "=l"(r) : "f"(x));
    return r;
}
__device__ __forceinline__ float2 up2(unsigned long long v) {
    float2 r;
    asm("mov.b64 {%0, %1}, %2;" : "=f"(r.x), "=f"(r.y) : "l"(v));
    return r;
}
__device__ __forceinline__ float silu_f(float x) {
    return x / (1.0f + __expf(-x));
}

// ============================================================================
// Kernel 1: h = silu(bn1(features @ W1))   [N,128] x [128,64] -> [N,64]
// 64 sites per block, 256 threads. Thread = (sg = t>>3 in [0,32), cg = t&7).
// Each thread: sites {sg, sg+32}, channels [cg*8, cg*8+8). 8 f32x2 accumulators.
// ============================================================================
#define K1_SF_STRIDE 132

__global__ __launch_bounds__(256) void k1_cv1(
    const float* __restrict__ feat,
    const float* __restrict__ W1,
    const float* __restrict__ g1, const float* __restrict__ b1,
    const float* __restrict__ m1, const float* __restrict__ v1)
{
    extern __shared__ float sm[];
    float* sW = sm;                 // 128*64 = 8192 floats
    float* sF = sm + 8192;          // 64 * 132 floats

    int t = threadIdx.x;
    int base = blockIdx.x * 64;

    // Load W1 (8192 floats = 2048 float4)
    {
        const float4* w4 = (const float4*)W1;
        float4* sw4 = (float4*)sW;
        #pragma unroll
        for (int i = 0; i < 8; i++) sw4[t + 256 * i] = w4[t + 256 * i];
    }
    // Load feature tile: 64 rows x 128 floats (float4 granules)
    for (int q = t; q < 64 * 32; q += 256) {
        int r = q >> 5, c4 = q & 31;
        int site = base + r;
        float4 v = make_float4(0.f, 0.f, 0.f, 0.f);
        if (site < NSITES) v = ((const float4*)feat)[site * 32 + c4];
        float* dst = sF + r * K1_SF_STRIDE + c4 * 4;
        dst[0] = v.x; dst[1] = v.y; dst[2] = v.z; dst[3] = v.w;
    }
    __syncthreads();

    int cg = t & 7;
    int sg = t >> 3;
    const float* f0 = sF + sg * K1_SF_STRIDE;
    const float* f1 = sF + (sg + 32) * K1_SF_STRIDE;

    unsigned long long acc[8];
    #pragma unroll
    for (int i = 0; i < 8; i++) acc[i] = 0ull;

    #pragma unroll 4
    for (int j4 = 0; j4 < 128; j4 += 4) {
        float4 a0 = *(const float4*)(f0 + j4);
        float4 a1 = *(const float4*)(f1 + j4);
        float a0v[4] = {a0.x, a0.y, a0.z, a0.w};
        float a1v[4] = {a1.x, a1.y, a1.z, a1.w};
        #pragma unroll
        for (int u = 0; u < 4; u++) {
            int j = j4 + u;
            const unsigned long long* wp =
                (const unsigned long long*)(sW + j * 64 + cg * 8);
            unsigned long long w0 = wp[0], w1 = wp[1], w2 = wp[2], w3 = wp[3];
            unsigned long long p0 = pk2(a0v[u]);
            unsigned long long p1 = pk2(a1v[u]);
            fma2(acc[0], p0, w0); fma2(acc[1], p0, w1);
            fma2(acc[2], p0, w2); fma2(acc[3], p0, w3);
            fma2(acc[4], p1, w0); fma2(acc[5], p1, w1);
            fma2(acc[6], p1, w2); fma2(acc[7], p1, w3);
        }
    }

    // BN1 + SiLU epilogue
    float sc[8], tb[8];
    #pragma unroll
    for (int c = 0; c < 8; c++) {
        int ch = cg * 8 + c;
        float s = g1[ch] * rsqrtf(v1[ch] + EPS);
        sc[c] = s;
        tb[c] = b1[ch] - m1[ch] * s;
    }
    #pragma unroll
    for (int half = 0; half < 2; half++) {
        int site = base + sg + half * 32;
        if (site < NSITES) {
            float o[8];
            #pragma unroll
            for (int i = 0; i < 4; i++) {
                float2 v = up2(acc[half * 4 + i]);
                o[2 * i] = v.x; o[2 * i + 1] = v.y;
            }
            #pragma unroll
            for (int c = 0; c < 8; c++) {
                float x = o[c] * sc[c] + tb[c];
                o[c] = silu_f(x);
            }
            float4* dst = (float4*)(g_h + site * CH + cg * 8);
            dst[0] = make_float4(o[0], o[1], o[2], o[3]);
            dst[1] = make_float4(o[4], o[5], o[6], o[7]);
        }
    }
}

// ============================================================================
// Kernel 2: fused cv2 (sparse 3x3 rulebook conv) + BN2/SiLU + cv3 + BN3 +
// residual + SiLU.  128 sites per block, 256 threads.
// ============================================================================
#define GAT_STRIDE 68
#define ACC_STRIDE 68

__global__ __launch_bounds__(256) void k2_cv23(
    const float* __restrict__ feat,
    const int* __restrict__ nbr,
    const float* __restrict__ W2,
    const float* __restrict__ W3,
    const float* __restrict__ g2, const float* __restrict__ b2,
    const float* __restrict__ m2, const float* __restrict__ v2,
    const float* __restrict__ g3, const float* __restrict__ b3,
    const float* __restrict__ m3, const float* __restrict__ v3,
    float* __restrict__ out)
{
    extern __shared__ float sm[];
    float* sAcc = sm;                   // 128 * 68 = 8704 floats
    float* sGat = sm + 8704;            // 128 * 68 = 8704 floats
    float* sW   = sm + 17408;           // 8192 floats (W2[k] then W3)
    int* lrow = (int*)(sm + 25600);     // 128
    int* lgat = lrow + 128;             // 128
    int* pcnt = lgat + 128;             // 1

    int t = threadIdx.x;
    int base = blockIdx.x * 128;

    // zero accumulator
    for (int q = t; q < 128 * ACC_STRIDE; q += 256) sAcc[q] = 0.f;

    int cg = t & 7;        // 8-channel group for cv2
    int rg = t >> 3;       // row group (32 rows per pass)

    for (int k = 0; k < 9; k++) {
        if (t == 0) *pcnt = 0;
        __syncthreads();
        // compact valid neighbors for this offset
        if (t < 128) {
            int site = base + t;
            if (site < NSITES) {
                int id = nbr[k * NSITES + site];
                if (id < NSITES) {
                    int p = atomicAdd(pcnt, 1);
                    lrow[p] = t;
                    lgat[p] = id;
                }
            }
        }
        // load W2[k] (4096 floats = 1024 float4)
        {
            const float4* w4 = (const float4*)(W2 + k * (CH * CH));
            float4* sw4 = (float4*)sW;
            #pragma unroll
            for (int i = 0; i < 4; i++) sw4[t + 256 * i] = w4[t + 256 * i];
        }
        __syncthreads();
        int m = *pcnt;

        // gather h rows of valid neighbors (float4 granules)
        for (int q = t; q < m * 16; q += 256) {
            int r = q >> 4, c4 = q & 15;
            float4 v = ((const float4*)g_h)[lgat[r] * 16 + c4];
            float* dst = sGat + r * GAT_STRIDE + c4 * 4;
            dst[0] = v.x; dst[1] = v.y; dst[2] = v.z; dst[3] = v.w;
        }
        __syncthreads();

        // compacted matmul: only m rows get computed (sparsity win)
        for (int r0 = 0; r0 < m; r0 += 32) {
            int r = r0 + rg;
            if (r < m) {
                unsigned long long acc[4] = {0ull, 0ull, 0ull, 0ull};
                const float* hr = sGat + r * GAT_STRIDE;
                #pragma unroll 4
                for (int j4 = 0; j4 < 64; j4 += 4) {
                    float4 av = *(const float4*)(hr + j4);
                    float avv[4] = {av.x, av.y, av.z, av.w};
                    #pragma unroll
                    for (int u = 0; u < 4; u++) {
                        int j = j4 + u;
                        const unsigned long long* wp =
                            (const unsigned long long*)(sW + j * 64 + cg * 8);
                        unsigned long long p = pk2(avv[u]);
                        fma2(acc[0], p, wp[0]); fma2(acc[1], p, wp[1]);
                        fma2(acc[2], p, wp[2]); fma2(acc[3], p, wp[3]);
                    }
                }
                float* ap = sAcc + lrow[r] * ACC_STRIDE + cg * 8;
                #pragma unroll
                for (int i = 0; i < 4; i++) {
                    float2 v = up2(acc[i]);
                    ap[2 * i]     += v.x;
                    ap[2 * i + 1] += v.y;
                }
            }
        }
        __syncthreads();
    }

    // BN2 + SiLU in place on sAcc
    for (int q = t; q < 128 * 64; q += 256) {
        int s = q >> 6, c = q & 63;
        float sc2 = g2[c] * rsqrtf(v2[c] + EPS);
        float tb2 = b2[c] - m2[c] * sc2;
        float x = sAcc[s * ACC_STRIDE + c] * sc2 + tb2;
        sAcc[s * ACC_STRIDE + c] = silu_f(x);
    }
    __syncthreads();

    // load W3 (64x128 = 8192 floats)
    {
        const float4* w4 = (const float4*)W3;
        float4* sw4 = (float4*)sW;
        #pragma unroll
        for (int i = 0; i < 8; i++) sw4[t + 256 * i] = w4[t + 256 * i];
    }
    __syncthreads();

    // cv3: [128,64] @ [64,128], thread = (sgrp = t>>4 -> 4 sites, cg16 = t&15 -> 8 ch)
    int cg16 = t & 15;
    int c0 = cg16 * 8;
    int sgrp = t >> 4;

    float sc3[8], tb3[8];
    #pragma unroll
    for (int c = 0; c < 8; c++) {
        int ch = c0 + c;
        float s = g3[ch] * rsqrtf(v3[ch] + EPS);
        sc3[c] = s;
        tb3[c] = b3[ch] - m3[ch] * s;
    }

    for (int pass = 0; pass < 2; pass++) {
        int sbase = pass * 64 + sgrp * 4;
        unsigned long long acc[4][4];
        #pragma unroll
        for (int i = 0; i < 4; i++)
            #pragma unroll
            for (int p = 0; p < 4; p++) acc[i][p] = 0ull;

        #pragma unroll 4
        for (int j = 0; j < 64; j++) {
            const unsigned long long* wp =
                (const unsigned long long*)(sW + j * 128 + c0);
            unsigned long long w0 = wp[0], w1 = wp[1], w2 = wp[2], w3v = wp[3];
            #pragma unroll
            for (int i = 0; i < 4; i++) {
                unsigned long long a = pk2(sAcc[(sbase + i) * ACC_STRIDE + j]);
                fma2(acc[i][0], a, w0); fma2(acc[i][1], a, w1);
                fma2(acc[i][2], a, w2); fma2(acc[i][3], a, w3v);
            }
        }

        #pragma unroll
        for (int i = 0; i < 4; i++) {
            int site = base + sbase + i;
            if (site < NSITES) {
                float o[8];
                #pragma unroll
                for (int p = 0; p < 4; p++) {
                    float2 v = up2(acc[i][p]);
                    o[2 * p] = v.x; o[2 * p + 1] = v.y;
                }
                const float4* fr = (const float4*)(feat + site * C2 + c0);
                float4 fA = fr[0], fB = fr[1];
                float fv[8] = {fA.x, fA.y, fA.z, fA.w, fB.x, fB.y, fB.z, fB.w};
                #pragma unroll
                for (int c = 0; c < 8; c++) {
                    float x = o[c] * sc3[c] + tb3[c] + fv[c];
                    o[c] = silu_f(x);
                }
                float4* dst = (float4*)(out + site * C2 + c0);
                dst[0] = make_float4(o[0], o[1], o[2], o[3]);
                dst[1] = make_float4(o[4], o[5], o[6], o[7]);
            }
        }
    }
}

// ============================================================================
// launch
// ============================================================================
extern "C" void kernel_launch(void* const* d_in, const int* in_sizes, int n_in,
                              void* d_out, int out_size) {
    const float* feat = (const float*)d_in[0];
    const int*   nbr  = (const int*)d_in[1];
    const float* W1   = (const float*)d_in[2];
    const float* W2   = (const float*)d_in[3];
    const float* W3   = (const float*)d_in[4];
    const float* g1 = (const float*)d_in[5];
    const float* b1 = (const float*)d_in[6];
    const float* m1 = (const float*)d_in[7];
    const float* v1 = (const float*)d_in[8];
    const float* g2 = (const float*)d_in[9];
    const float* b2 = (const float*)d_in[10];
    const float* m2 = (const float*)d_in[11];
    const float* v2 = (const float*)d_in[12];
    const float* g3 = (const float*)d_in[13];
    const float* b3 = (const float*)d_in[14];
    const float* m3 = (const float*)d_in[15];
    const float* v3 = (const float*)d_in[16];
    float* out = (float*)d_out;

    const int smem1 = (8192 + 64 * K1_SF_STRIDE) * 4;                  // 66560
    const int smem2 = (128 * ACC_STRIDE + 128 * GAT_STRIDE + 8192) * 4 // 102400
                      + 257 * 4 + 4;                                   // lists+cnt
    cudaFuncSetAttribute(k1_cv1, cudaFuncAttributeMaxDynamicSharedMemorySize, smem1);
    cudaFuncSetAttribute(k2_cv23, cudaFuncAttributeMaxDynamicSharedMemorySize, smem2);

    int grid1 = (NSITES + 63) / 64;     // 7813
    int grid2 = (NSITES + 127) / 128;   // 3907

    k1_cv1<<<grid1, 256, smem1>>>(feat, W1, g1, b1, m1, v1);
    k2_cv23<<<grid2, 256, smem2>>>(feat, nbr, W2, W3,
                                   g2, b2, m2, v2, g3, b3, m3, v3, out);
}

// round 2
// speedup vs baseline: 1.4277x; 1.4277x over previous
#include <cuda_runtime.h>
#include <cuda_bf16.h>

#define NSITES 500000
#define C1 128
#define CH 64
#define C2 128
#define EPS 1e-5f

// h = silu(bn1(features @ W1)), [N, 64]
__device__ float g_h[NSITES * CH];

// ---------- packed f32x2 helpers ----------
__device__ __forceinline__ void fma2(unsigned long long& d, unsigned long long a, unsigned long long b) {
    asm("fma.rn.f32x2 %0, %1, %2, %0;" : "+l"(d) : "l"(a), "l"(b));
}
__device__ __forceinline__ unsigned long long pk2(float x) {
    unsigned long long r;
    asm("mov.b64 %0, {%1, %1};" : "=l"(r) : "f"(x));
    return r;
}
__device__ __forceinline__ float2 up2(unsigned long long v) {
    float2 r;
    asm("mov.b64 {%0, %1}, %2;" : "=f"(r.x), "=f"(r.y) : "l"(v));
    return r;
}
__device__ __forceinline__ float silu_f(float x) {
    return x / (1.0f + __expf(-x));
}

// ============================================================================
// Kernel 1: h = silu(bn1(features @ W1))   [N,128] x [128,64] -> [N,64]
// 128 sites per block, 256 threads. cg = t&7 (8 col groups x 8 ch),
// rg = t>>3 (32 row groups). Thread handles rows {rg, rg+32, rg+64, rg+96}
// (stride-32 assignment -> conflict-free smem reads) x 8 channels.
// ============================================================================
#define K1_STRIDE 132

__global__ __launch_bounds__(256, 2) void k1_cv1(
    const float* __restrict__ feat,
    const float* __restrict__ W1,
    const float* __restrict__ g1, const float* __restrict__ b1,
    const float* __restrict__ m1, const float* __restrict__ v1)
{
    extern __shared__ float sm[];
    float* sW = sm;                 // 128*64 = 8192 floats
    float* sF = sm + 8192;          // 128 * 132 floats

    int t = threadIdx.x;
    int base = blockIdx.x * 128;

    // Load W1 (8192 floats = 2048 float4)
    {
        const float4* w4 = (const float4*)W1;
        float4* sw4 = (float4*)sW;
        #pragma unroll
        for (int i = 0; i < 8; i++) sw4[t + 256 * i] = w4[t + 256 * i];
    }
    // Load feature tile: 128 rows x 128 floats (float4 granules)
    for (int q = t; q < 128 * 32; q += 256) {
        int r = q >> 5, c4 = q & 31;
        int site = base + r;
        float4 v = make_float4(0.f, 0.f, 0.f, 0.f);
        if (site < NSITES) v = ((const float4*)feat)[site * 32 + c4];
        float* dst = sF + r * K1_STRIDE + c4 * 4;
        dst[0] = v.x; dst[1] = v.y; dst[2] = v.z; dst[3] = v.w;
    }
    __syncthreads();

    int cg = t & 7;
    int rg = t >> 3;

    unsigned long long acc[4][4];
    #pragma unroll
    for (int i = 0; i < 4; i++)
        #pragma unroll
        for (int p = 0; p < 4; p++) acc[i][p] = 0ull;

    #pragma unroll 2
    for (int j4 = 0; j4 < 128; j4 += 4) {
        float4 a[4];
        #pragma unroll
        for (int i = 0; i < 4; i++)
            a[i] = *(const float4*)(sF + (rg + 32 * i) * K1_STRIDE + j4);
        #pragma unroll
        for (int u = 0; u < 4; u++) {
            const unsigned long long* wp =
                (const unsigned long long*)(sW + (j4 + u) * 64 + cg * 8);
            unsigned long long w0 = wp[0], w1 = wp[1], w2 = wp[2], w3 = wp[3];
            #pragma unroll
            for (int i = 0; i < 4; i++) {
                float av = (u == 0) ? a[i].x : (u == 1) ? a[i].y : (u == 2) ? a[i].z : a[i].w;
                unsigned long long p = pk2(av);
                fma2(acc[i][0], p, w0); fma2(acc[i][1], p, w1);
                fma2(acc[i][2], p, w2); fma2(acc[i][3], p, w3);
            }
        }
    }

    // BN1 + SiLU epilogue
    float sc[8], tb[8];
    #pragma unroll
    for (int c = 0; c < 8; c++) {
        int ch = cg * 8 + c;
        float s = g1[ch] * rsqrtf(v1[ch] + EPS);
        sc[c] = s;
        tb[c] = b1[ch] - m1[ch] * s;
    }
    #pragma unroll
    for (int i = 0; i < 4; i++) {
        int site = base + rg + 32 * i;
        if (site < NSITES) {
            float o[8];
            #pragma unroll
            for (int p = 0; p < 4; p++) {
                float2 v = up2(acc[i][p]);
                o[2 * p] = v.x; o[2 * p + 1] = v.y;
            }
            #pragma unroll
            for (int c = 0; c < 8; c++)
                o[c] = silu_f(o[c] * sc[c] + tb[c]);
            float4* dst = (float4*)(g_h + site * CH + cg * 8);
            dst[0] = make_float4(o[0], o[1], o[2], o[3]);
            dst[1] = make_float4(o[4], o[5], o[6], o[7]);
        }
    }
}

// ============================================================================
// Kernel 2: fused cv2 (sparse 3x3 rulebook conv) + BN2/SiLU + cv3 + BN3 +
// residual + SiLU.  128 sites per block, 256 threads.
// cv2 matmul: 4 rows x 8 cols per thread (rows 4*rg+i over compacted list).
// ============================================================================
#define GAT_STRIDE 68
#define ACC_STRIDE 68

__global__ __launch_bounds__(256, 2) void k2_cv23(
    const float* __restrict__ feat,
    const int* __restrict__ nbr,
    const float* __restrict__ W2,
    const float* __restrict__ W3,
    const float* __restrict__ g2, const float* __restrict__ b2,
    const float* __restrict__ m2, const float* __restrict__ v2,
    const float* __restrict__ g3, const float* __restrict__ b3,
    const float* __restrict__ m3, const float* __restrict__ v3,
    float* __restrict__ out)
{
    extern __shared__ float sm[];
    float* sAcc = sm;                   // 128 * 68 = 8704 floats
    float* sGat = sm + 8704;            // 128 * 68 = 8704 floats
    float* sW   = sm + 17408;           // 8192 floats (W2[k] / later W3)
    int* lrow = (int*)(sm + 25600);     // 128
    int* lgat = lrow + 128;             // 128
    int* pcnt = lgat + 128;             // 1

    int t = threadIdx.x;
    int lane = t & 31;
    int base = blockIdx.x * 128;

    // zero accumulator
    for (int q = t; q < 128 * ACC_STRIDE; q += 256) sAcc[q] = 0.f;

    int cg = t & 7;        // 8-channel group for cv2
    int rg = t >> 3;       // row group: rows 4*rg .. 4*rg+3

    if (t == 0) *pcnt = 0;
    __syncthreads();

    for (int k = 0; k < 9; k++) {
        // compact valid neighbors via warp ballot (threads 0..127 = 4 full warps)
        if (t < 128) {
            int site = base + t;
            int id = NSITES;
            if (site < NSITES) id = nbr[k * NSITES + site];
            bool valid = (id < NSITES);
            unsigned mask = __ballot_sync(0xffffffffu, valid);
            int cnt = __popc(mask);
            int wbase = 0;
            if (lane == 0 && cnt) wbase = atomicAdd(pcnt, cnt);
            wbase = __shfl_sync(0xffffffffu, wbase, 0);
            if (valid) {
                int pos = wbase + __popc(mask & ((1u << lane) - 1u));
                lrow[pos] = t;
                lgat[pos] = id;
            }
        }
        // load W2[k] (4096 floats = 1024 float4)
        {
            const float4* w4 = (const float4*)(W2 + k * (CH * CH));
            float4* sw4 = (float4*)sW;
            #pragma unroll
            for (int i = 0; i < 4; i++) sw4[t + 256 * i] = w4[t + 256 * i];
        }
        __syncthreads();
        int m = *pcnt;

        // gather h rows of valid neighbors (float4 granules)
        for (int q = t; q < m * 16; q += 256) {
            int r = q >> 4, c4 = q & 15;
            float4 v = ((const float4*)g_h)[lgat[r] * 16 + c4];
            float* dst = sGat + r * GAT_STRIDE + c4 * 4;
            dst[0] = v.x; dst[1] = v.y; dst[2] = v.z; dst[3] = v.w;
        }
        __syncthreads();

        // compacted matmul: rows 4*rg+i, only warps with rows < m are busy
        if (4 * rg < m) {
            int rr[4];
            #pragma unroll
            for (int i = 0; i < 4; i++) {
                int r = 4 * rg + i;
                rr[i] = (r < m) ? r : (m - 1);
            }
            unsigned long long acc[4][4];
            #pragma unroll
            for (int i = 0; i < 4; i++)
                #pragma unroll
                for (int p = 0; p < 4; p++) acc[i][p] = 0ull;

            #pragma unroll 2
            for (int j4 = 0; j4 < 64; j4 += 4) {
                float4 a[4];
                #pragma unroll
                for (int i = 0; i < 4; i++)
                    a[i] = *(const float4*)(sGat + rr[i] * GAT_STRIDE + j4);
                #pragma unroll
                for (int u = 0; u < 4; u++) {
                    const unsigned long long* wp =
                        (const unsigned long long*)(sW + (j4 + u) * 64 + cg * 8);
                    unsigned long long w0 = wp[0], w1 = wp[1], w2 = wp[2], w3 = wp[3];
                    #pragma unroll
                    for (int i = 0; i < 4; i++) {
                        float av = (u == 0) ? a[i].x : (u == 1) ? a[i].y : (u == 2) ? a[i].z : a[i].w;
                        unsigned long long p = pk2(av);
                        fma2(acc[i][0], p, w0); fma2(acc[i][1], p, w1);
                        fma2(acc[i][2], p, w2); fma2(acc[i][3], p, w3);
                    }
                }
            }
            #pragma unroll
            for (int i = 0; i < 4; i++) {
                if (4 * rg + i < m) {
                    float* ap = sAcc + lrow[rr[i]] * ACC_STRIDE + cg * 8;
                    #pragma unroll
                    for (int p = 0; p < 4; p++) {
                        float2 v = up2(acc[i][p]);
                        ap[2 * p]     += v.x;
                        ap[2 * p + 1] += v.y;
                    }
                }
            }
        }
        if (t == 0) *pcnt = 0;   // reset for next k (pcnt already consumed)
        __syncthreads();
    }

    // BN2 + SiLU in place on sAcc
    for (int q = t; q < 128 * 64; q += 256) {
        int s = q >> 6, c = q & 63;
        float sc2 = g2[c] * rsqrtf(v2[c] + EPS);
        float tb2 = b2[c] - m2[c] * sc2;
        float x = sAcc[s * ACC_STRIDE + c] * sc2 + tb2;
        sAcc[s * ACC_STRIDE + c] = silu_f(x);
    }
    __syncthreads();

    // load W3 (64x128 = 8192 floats)
    {
        const float4* w4 = (const float4*)W3;
        float4* sw4 = (float4*)sW;
        #pragma unroll
        for (int i = 0; i < 8; i++) sw4[t + 256 * i] = w4[t + 256 * i];
    }
    __syncthreads();

    // cv3: [128,64] @ [64,128]; thread = (sgrp = t>>4 -> 4 sites, cg16 = t&15 -> 8 ch)
    int cg16 = t & 15;
    int c0 = cg16 * 8;
    int sgrp = t >> 4;

    float sc3[8], tb3[8];
    #pragma unroll
    for (int c = 0; c < 8; c++) {
        int ch = c0 + c;
        float s = g3[ch] * rsqrtf(v3[ch] + EPS);
        sc3[c] = s;
        tb3[c] = b3[ch] - m3[ch] * s;
    }

    for (int pass = 0; pass < 2; pass++) {
        int sbase = pass * 64 + sgrp * 4;
        unsigned long long acc[4][4];
        #pragma unroll
        for (int i = 0; i < 4; i++)
            #pragma unroll
            for (int p = 0; p < 4; p++) acc[i][p] = 0ull;

        #pragma unroll 2
        for (int j4 = 0; j4 < 64; j4 += 4) {
            float4 a[4];
            #pragma unroll
            for (int i = 0; i < 4; i++)
                a[i] = *(const float4*)(sAcc + (sbase + i) * ACC_STRIDE + j4);
            #pragma unroll
            for (int u = 0; u < 4; u++) {
                const unsigned long long* wp =
                    (const unsigned long long*)(sW + (j4 + u) * 128 + c0);
                unsigned long long w0 = wp[0], w1 = wp[1], w2 = wp[2], w3v = wp[3];
                #pragma unroll
                for (int i = 0; i < 4; i++) {
                    float av = (u == 0) ? a[i].x : (u == 1) ? a[i].y : (u == 2) ? a[i].z : a[i].w;
                    unsigned long long p = pk2(av);
                    fma2(acc[i][0], p, w0); fma2(acc[i][1], p, w1);
                    fma2(acc[i][2], p, w2); fma2(acc[i][3], p, w3v);
                }
            }
        }

        #pragma unroll
        for (int i = 0; i < 4; i++) {
            int site = base + sbase + i;
            if (site < NSITES) {
                float o[8];
                #pragma unroll
                for (int p = 0; p < 4; p++) {
                    float2 v = up2(acc[i][p]);
                    o[2 * p] = v.x; o[2 * p + 1] = v.y;
                }
                const float4* fr = (const float4*)(feat + site * C2 + c0);
                float4 fA = fr[0], fB = fr[1];
                float fv[8] = {fA.x, fA.y, fA.z, fA.w, fB.x, fB.y, fB.z, fB.w};
                #pragma unroll
                for (int c = 0; c < 8; c++)
                    o[c] = silu_f(o[c] * sc3[c] + tb3[c] + fv[c]);
                float4* dst = (float4*)(out + site * C2 + c0);
                dst[0] = make_float4(o[0], o[1], o[2], o[3]);
                dst[1] = make_float4(o[4], o[5], o[6], o[7]);
            }
        }
    }
}

// ============================================================================
// launch
// ============================================================================
extern "C" void kernel_launch(void* const* d_in, const int* in_sizes, int n_in,
                              void* d_out, int out_size) {
    const float* feat = (const float*)d_in[0];
    const int*   nbr  = (const int*)d_in[1];
    const float* W1   = (const float*)d_in[2];
    const float* W2   = (const float*)d_in[3];
    const float* W3   = (const float*)d_in[4];
    const float* g1 = (const float*)d_in[5];
    const float* b1 = (const float*)d_in[6];
    const float* m1 = (const float*)d_in[7];
    const float* v1 = (const float*)d_in[8];
    const float* g2 = (const float*)d_in[9];
    const float* b2 = (const float*)d_in[10];
    const float* m2 = (const float*)d_in[11];
    const float* v2 = (const float*)d_in[12];
    const float* g3 = (const float*)d_in[13];
    const float* b3 = (const float*)d_in[14];
    const float* m3 = (const float*)d_in[15];
    const float* v3 = (const float*)d_in[16];
    float* out = (float*)d_out;

    const int smem1 = (8192 + 128 * K1_STRIDE) * 4;                     // 100352
    const int smem2 = (128 * ACC_STRIDE + 128 * GAT_STRIDE + 8192) * 4
                      + 257 * 4 + 4;                                    // ~103.5 KB
    cudaFuncSetAttribute(k1_cv1, cudaFuncAttributeMaxDynamicSharedMemorySize, smem1);
    cudaFuncSetAttribute(k2_cv23, cudaFuncAttributeMaxDynamicSharedMemorySize, smem2);

    int grid = (NSITES + 127) / 128;    // 3907

    k1_cv1<<<grid, 256, smem1>>>(feat, W1, g1, b1, m1, v1);
    k2_cv23<<<grid, 256, smem2>>>(feat, nbr, W2, W3,
                                  g2, b2, m2, v2, g3, b3, m3, v3, out);
}